// round 1
// baseline (speedup 1.0000x reference)
#include <cuda_runtime.h>
#include <math.h>

// Problem constants
#define BB    4
#define CC    256
#define HHH   64
#define WWW   64
#define HWSZ  4096
#define NGRP  32
#define CPG   8

// ---------------- scratch (device globals; no allocation allowed) ----------------
__device__ float g_a  [BB*CC*HWSZ];      // groupnorm(+silu) output
__device__ float g_h  [BB*CC*HWSZ];      // conv1 output / modulated h
__device__ float g_xr [BB*CC*HWSZ];      // residual branch output
__device__ float g_qkv[BB*3*CC*HWSZ];    // qkv projections [b][3C][HW]
__device__ float g_ao [BB*CC*HWSZ];      // attention output [b][C][HW]
__device__ float g_gb [BB*2*CC];         // FiLM gamma/beta
__device__ float g_w1t[CC*CC*12];        // conv1 weights transposed [ic][oc][12]
__device__ float g_w2t[CC*CC*12];        // conv2 weights transposed

// ---------------- weight transpose: w[oc][ic][9] -> wt[ic][oc*12+k] ----------------
__global__ void wtrans_kernel(const float* __restrict__ w, float* __restrict__ wt) {
    int i = blockIdx.x * 256 + threadIdx.x;
    if (i < CC * CC) {
        int oc = i >> 8, ic = i & 255;
        const float* s = w + (size_t)(oc * CC + ic) * 9;
        float* d = wt + (size_t)ic * CC * 12 + oc * 12;
        #pragma unroll
        for (int k = 0; k < 9; k++) d[k] = s[k];
        d[9] = 0.f; d[10] = 0.f; d[11] = 0.f;
    }
}

// ---------------- GroupNorm (+ optional SiLU) ----------------
// grid: B*NGRP blocks, 256 threads
__global__ void gn_kernel(const float* __restrict__ x, const float* __restrict__ sc,
                          const float* __restrict__ bi, float* __restrict__ y, int dosilu) {
    __shared__ float rs[256], rq[256];
    __shared__ float mv[2];
    int bg = blockIdx.x;
    int b = bg >> 5, g = bg & 31;
    const float* xp = x + (size_t)(b * CC + g * CPG) * HWSZ;
    float* yp = y + (size_t)(b * CC + g * CPG) * HWSZ;
    int tid = threadIdx.x;
    float sum = 0.f, sq = 0.f;
    for (int i = tid; i < CPG * HWSZ; i += 256) {
        float v = xp[i];
        sum += v; sq += v * v;
    }
    rs[tid] = sum; rq[tid] = sq;
    __syncthreads();
    for (int st = 128; st > 0; st >>= 1) {
        if (tid < st) { rs[tid] += rs[tid + st]; rq[tid] += rq[tid + st]; }
        __syncthreads();
    }
    if (tid == 0) {
        float m = rs[0] * (1.f / 32768.f);
        float var = rq[0] * (1.f / 32768.f) - m * m;
        mv[0] = m; mv[1] = rsqrtf(var + 1e-5f);
    }
    __syncthreads();
    float m = mv[0], inv = mv[1];
    for (int i = tid; i < CPG * HWSZ; i += 256) {
        int c = g * CPG + (i >> 12);
        float v = (xp[i] - m) * inv * sc[c] + bi[c];
        if (dosilu) v = v / (1.f + __expf(-v));
        yp[i] = v;
    }
}

// ---------------- 3x3 SAME conv, optional residual add ----------------
// grid: (H, 2, B); block 256. Block computes one output row, 128 output channels.
// wt layout: [ic][oc*12 + k] (k<9 valid, 9..11 zero)
__global__ void __launch_bounds__(256) conv3x3_kernel(
    const float* __restrict__ x, const float* __restrict__ wt,
    const float* __restrict__ bias, const float* __restrict__ res,
    float* __restrict__ y) {
    __shared__ float s_in[3][66];
    __shared__ float s_w[128 * 12];
    int h = blockIdx.x, ob = blockIdx.y * 128, b = blockIdx.z;
    int tid = threadIdx.x;
    int pxg = tid & 15;   // pixel group: pixels pxg*4 .. +3
    int ocg = tid >> 4;   // oc group:   oc ob+ocg*8 .. +7
    float acc[8][4];
    #pragma unroll
    for (int o = 0; o < 8; o++)
        #pragma unroll
        for (int p = 0; p < 4; p++) acc[o][p] = 0.f;
    const float* xb = x + (size_t)b * CC * HWSZ + h * WWW;
    for (int ic = 0; ic < CC; ic++) {
        __syncthreads();
        if (tid < 198) {
            int r = tid / 66, xx = tid % 66;
            int hh2 = h + r - 1, col = xx - 1;
            float v = 0.f;
            if (hh2 >= 0 && hh2 < HHH && col >= 0 && col < WWW)
                v = xb[(size_t)ic * HWSZ + (r - 1) * WWW + col];
            s_in[r][xx] = v;
        }
        const float* wp = wt + (size_t)ic * CC * 12 + ob * 12;
        for (int l = tid; l < 128 * 12; l += 256) s_w[l] = wp[l];
        __syncthreads();
        float inr[3][6];
        #pragma unroll
        for (int r = 0; r < 3; r++)
            #pragma unroll
            for (int j = 0; j < 6; j++) inr[r][j] = s_in[r][pxg * 4 + j];
        #pragma unroll
        for (int o = 0; o < 8; o++) {
            const float* wo = &s_w[(ocg * 8 + o) * 12];
            #pragma unroll
            for (int r = 0; r < 3; r++) {
                float w0 = wo[r * 3 + 0], w1 = wo[r * 3 + 1], w2 = wo[r * 3 + 2];
                #pragma unroll
                for (int p = 0; p < 4; p++)
                    acc[o][p] += w0 * inr[r][p] + w1 * inr[r][p + 1] + w2 * inr[r][p + 2];
            }
        }
    }
    #pragma unroll
    for (int o = 0; o < 8; o++) {
        int oc = ob + ocg * 8 + o;
        float bv = bias[oc];
        #pragma unroll
        for (int p = 0; p < 4; p++) {
            size_t idx = (size_t)(b * CC + oc) * HWSZ + h * WWW + pxg * 4 + p;
            float v = acc[o][p] + bv;
            if (res) v += res[idx];
            y[idx] = v;
        }
    }
}

// ---------------- FiLM mlp: gb[b,j] = silu(te[b,:]) . mlp_w[j,:] + mlp_b[j] ----------------
// grid (B, 4), block 128
__global__ void film_mlp_kernel(const float* __restrict__ te, const float* __restrict__ w,
                                const float* __restrict__ bi, float* __restrict__ gb) {
    __shared__ float s_te[256];
    int b = blockIdx.x, tid = threadIdx.x;
    for (int i = tid; i < 256; i += 128) {
        float v = te[b * 256 + i];
        s_te[i] = v / (1.f + __expf(-v));
    }
    __syncthreads();
    int j = blockIdx.y * 128 + tid;
    const float* wr = w + (size_t)j * 256;
    float acc = bi[j];
    for (int t = 0; t < 256; t++) acc += s_te[t] * wr[t];
    gb[b * 512 + j] = acc;
}

// ---------------- FiLM apply: h = (1+gamma)*h + beta ----------------
__global__ void film_apply_kernel(float* __restrict__ hbuf, const float* __restrict__ gb) {
    int i = blockIdx.x * 256 + threadIdx.x;
    int b = i >> 20;           // C*HW = 2^20
    int c = (i >> 12) & 255;
    hbuf[i] = (1.f + gb[b * 512 + c]) * hbuf[i] + gb[b * 512 + 256 + c];
}

// ---------------- GEMM: Y[b][o][p] = sum_c W[o][c] * X[b][c][p] (+bias +res) ----------------
// grid: (HW/64, O/64, B), block 256, 64x64 tile, 4x4 microtile
__global__ void __launch_bounds__(256) gemm_kernel(
    const float* __restrict__ W, const float* __restrict__ X,
    const float* __restrict__ bias, const float* __restrict__ res,
    float* __restrict__ Y, int O) {
    __shared__ float sA[16][68];
    __shared__ float sB[16][68];
    int b = blockIdx.z;
    const float* Xb = X + (size_t)b * CC * HWSZ;
    float* Yb = Y + (size_t)b * O * HWSZ;
    const float* Rb = res ? (res + (size_t)b * O * HWSZ) : (const float*)0;
    int o0 = blockIdx.y * 64, p0 = blockIdx.x * 64;
    int tid = threadIdx.x, tx = tid & 15, ty = tid >> 4;
    float acc[4][4];
    #pragma unroll
    for (int i = 0; i < 4; i++)
        #pragma unroll
        for (int j = 0; j < 4; j++) acc[i][j] = 0.f;
    for (int k0 = 0; k0 < CC; k0 += 16) {
        for (int l = tid; l < 1024; l += 256) {
            int o = l >> 4, kk = l & 15;
            sA[kk][o] = W[(size_t)(o0 + o) * CC + k0 + kk];
        }
        for (int l = tid; l < 1024; l += 256) {
            int kk = l >> 6, p = l & 63;
            sB[kk][p] = Xb[(size_t)(k0 + kk) * HWSZ + p0 + p];
        }
        __syncthreads();
        #pragma unroll
        for (int kk = 0; kk < 16; kk++) {
            float a[4], bb[4];
            #pragma unroll
            for (int i = 0; i < 4; i++) a[i] = sA[kk][ty * 4 + i];
            #pragma unroll
            for (int j = 0; j < 4; j++) bb[j] = sB[kk][tx * 4 + j];
            #pragma unroll
            for (int i = 0; i < 4; i++)
                #pragma unroll
                for (int j = 0; j < 4; j++) acc[i][j] += a[i] * bb[j];
        }
        __syncthreads();
    }
    #pragma unroll
    for (int i = 0; i < 4; i++) {
        int o = o0 + ty * 4 + i;
        float bv = bias ? bias[o] : 0.f;
        #pragma unroll
        for (int j = 0; j < 4; j++) {
            size_t idx = (size_t)o * HWSZ + p0 + tx * 4 + j;
            float v = acc[i][j] + bv;
            if (res) v += Rb[idx];
            Yb[idx] = v;
        }
    }
}

// ---------------- Flash attention: n_head=1, dim=256, scale 1/16 ----------------
// grid: (HW/64, B), block 256. Dynamic smem: sQ[256*64] sK[16*68] sP[64*68] sV[16*68]
__global__ void __launch_bounds__(256) attn_kernel(const float* __restrict__ qkv,
                                                   float* __restrict__ out) {
    extern __shared__ float smem[];
    float* sQ = smem;                 // [c][i] 256*64
    float* sK = sQ + 256 * 64;        // [cc][j] 16*68
    float* sP = sK + 16 * 68;         // [i][j]  64*68
    float* sV = sP + 64 * 68;         // [jj][d] 16*68
    int b = blockIdx.y, q0 = blockIdx.x * 64;
    const float* qp = qkv + (size_t)b * 3 * CC * HWSZ;
    const float* kp = qp + (size_t)CC * HWSZ;
    const float* vp = qp + (size_t)2 * CC * HWSZ;
    int tid = threadIdx.x, tx = tid & 15, ty = tid >> 4;

    for (int l = tid; l < 256 * 64; l += 256) {
        int c = l >> 6, i = l & 63;
        sQ[c * 64 + i] = qp[(size_t)c * HWSZ + q0 + i] * 0.0625f;
    }
    float m[4], lsum[4];
    float Oacc[4][4][4];  // [dchunk][i][dj]
    #pragma unroll
    for (int i = 0; i < 4; i++) { m[i] = -1e30f; lsum[i] = 0.f; }
    #pragma unroll
    for (int dc = 0; dc < 4; dc++)
        #pragma unroll
        for (int i = 0; i < 4; i++)
            #pragma unroll
            for (int dj = 0; dj < 4; dj++) Oacc[dc][i][dj] = 0.f;
    __syncthreads();

    for (int t0 = 0; t0 < HWSZ; t0 += 64) {
        // ---- scores S = (Q/16)^T K, 64x64 tile ----
        float S[4][4];
        #pragma unroll
        for (int i = 0; i < 4; i++)
            #pragma unroll
            for (int j = 0; j < 4; j++) S[i][j] = 0.f;
        for (int c0 = 0; c0 < 256; c0 += 16) {
            __syncthreads();
            for (int l = tid; l < 1024; l += 256) {
                int cc = l >> 6, j = l & 63;
                sK[cc * 68 + j] = kp[(size_t)(c0 + cc) * HWSZ + t0 + j];
            }
            __syncthreads();
            #pragma unroll
            for (int cc = 0; cc < 16; cc++) {
                float a[4], bb[4];
                #pragma unroll
                for (int i = 0; i < 4; i++) a[i] = sQ[(c0 + cc) * 64 + ty * 4 + i];
                #pragma unroll
                for (int j = 0; j < 4; j++) bb[j] = sK[cc * 68 + tx * 4 + j];
                #pragma unroll
                for (int i = 0; i < 4; i++)
                    #pragma unroll
                    for (int j = 0; j < 4; j++) S[i][j] += a[i] * bb[j];
            }
        }
        // ---- online softmax (row state across 16 tx lanes via shuffles) ----
        float alpha[4];
        #pragma unroll
        for (int i = 0; i < 4; i++) {
            float rm = fmaxf(fmaxf(S[i][0], S[i][1]), fmaxf(S[i][2], S[i][3]));
            #pragma unroll
            for (int off = 1; off < 16; off <<= 1)
                rm = fmaxf(rm, __shfl_xor_sync(0xffffffffu, rm, off));
            float mn = fmaxf(m[i], rm);
            alpha[i] = __expf(m[i] - mn);
            float rs = 0.f;
            #pragma unroll
            for (int j = 0; j < 4; j++) {
                S[i][j] = __expf(S[i][j] - mn);
                rs += S[i][j];
            }
            #pragma unroll
            for (int off = 1; off < 16; off <<= 1)
                rs += __shfl_xor_sync(0xffffffffu, rs, off);
            lsum[i] = lsum[i] * alpha[i] + rs;
            m[i] = mn;
        }
        #pragma unroll
        for (int dc = 0; dc < 4; dc++)
            #pragma unroll
            for (int i = 0; i < 4; i++)
                #pragma unroll
                for (int dj = 0; dj < 4; dj++) Oacc[dc][i][dj] *= alpha[i];
        __syncthreads();   // prior PV phase done reading sP
        #pragma unroll
        for (int i = 0; i < 4; i++)
            #pragma unroll
            for (int j = 0; j < 4; j++)
                sP[(ty * 4 + i) * 68 + tx * 4 + j] = S[i][j];
        __syncthreads();
        // ---- O += P @ V^T  (V stored [d][t]) ----
        for (int j0 = 0; j0 < 64; j0 += 16) {
            for (int d0 = 0; d0 < 256; d0 += 64) {
                __syncthreads();
                for (int l = tid; l < 1024; l += 256) {
                    int dd = l >> 4, jj = l & 15;
                    sV[jj * 68 + dd] = vp[(size_t)(d0 + dd) * HWSZ + t0 + j0 + jj];
                }
                __syncthreads();
                int dc = d0 >> 6;
                #pragma unroll
                for (int jj = 0; jj < 16; jj++) {
                    float p4[4], v4[4];
                    #pragma unroll
                    for (int i = 0; i < 4; i++) p4[i] = sP[(ty * 4 + i) * 68 + j0 + jj];
                    #pragma unroll
                    for (int dj = 0; dj < 4; dj++) v4[dj] = sV[jj * 68 + tx * 4 + dj];
                    #pragma unroll
                    for (int i = 0; i < 4; i++)
                        #pragma unroll
                        for (int dj = 0; dj < 4; dj++)
                            Oacc[dc][i][dj] += p4[i] * v4[dj];
                }
            }
        }
    }
    // ---- epilogue: normalize, write out [b][d][s] ----
    float invl[4];
    #pragma unroll
    for (int i = 0; i < 4; i++) invl[i] = 1.f / lsum[i];
    #pragma unroll
    for (int dc = 0; dc < 4; dc++)
        #pragma unroll
        for (int i = 0; i < 4; i++)
            #pragma unroll
            for (int dj = 0; dj < 4; dj++) {
                int d = dc * 64 + tx * 4 + dj;
                out[(size_t)b * CC * HWSZ + (size_t)d * HWSZ + q0 + ty * 4 + i] =
                    Oacc[dc][i][dj] * invl[i];
            }
}

// ---------------- host launch ----------------
extern "C" void kernel_launch(void* const* d_in, const int* in_sizes, int n_in,
                              void* d_out, int out_size) {
    const float* x       = (const float*)d_in[0];
    const float* te      = (const float*)d_in[1];
    const float* gn1_s   = (const float*)d_in[2];
    const float* gn1_b   = (const float*)d_in[3];
    const float* conv1_w = (const float*)d_in[4];
    const float* conv1_b = (const float*)d_in[5];
    const float* mlp_w   = (const float*)d_in[6];
    const float* mlp_b   = (const float*)d_in[7];
    const float* gn2_s   = (const float*)d_in[8];
    const float* gn2_b   = (const float*)d_in[9];
    const float* conv2_w = (const float*)d_in[10];
    const float* conv2_b = (const float*)d_in[11];
    const float* gnA_s   = (const float*)d_in[12];
    const float* gnA_b   = (const float*)d_in[13];
    const float* qkv_w   = (const float*)d_in[14];
    const float* out_w   = (const float*)d_in[15];
    const float* out_b   = (const float*)d_in[16];
    float* out = (float*)d_out;

    float *a, *h, *xr, *qkv, *ao, *gb, *w1t, *w2t;
    cudaGetSymbolAddress((void**)&a,   g_a);
    cudaGetSymbolAddress((void**)&h,   g_h);
    cudaGetSymbolAddress((void**)&xr,  g_xr);
    cudaGetSymbolAddress((void**)&qkv, g_qkv);
    cudaGetSymbolAddress((void**)&ao,  g_ao);
    cudaGetSymbolAddress((void**)&gb,  g_gb);
    cudaGetSymbolAddress((void**)&w1t, g_w1t);
    cudaGetSymbolAddress((void**)&w2t, g_w2t);

    static int attr_set = 0;
    if (!attr_set) {
        cudaFuncSetAttribute(attn_kernel, cudaFuncAttributeMaxDynamicSharedMemorySize,
                             (int)((256 * 64 + 16 * 68 + 64 * 68 + 16 * 68) * sizeof(float)));
        attr_set = 1;
    }
    size_t attn_smem = (256 * 64 + 16 * 68 + 64 * 68 + 16 * 68) * sizeof(float);

    // weight transposes
    wtrans_kernel<<<256, 256>>>(conv1_w, w1t);
    wtrans_kernel<<<256, 256>>>(conv2_w, w2t);

    // ResNet block
    gn_kernel<<<BB * NGRP, 256>>>(x, gn1_s, gn1_b, a, 1);
    conv3x3_kernel<<<dim3(HHH, 2, BB), 256>>>(a, w1t, conv1_b, (const float*)0, h);
    film_mlp_kernel<<<dim3(BB, 4), 128>>>(te, mlp_w, mlp_b, gb);
    film_apply_kernel<<<BB * CC * HWSZ / 256, 256>>>(h, gb);
    gn_kernel<<<BB * NGRP, 256>>>(h, gn2_s, gn2_b, a, 1);
    conv3x3_kernel<<<dim3(HHH, 2, BB), 256>>>(a, w2t, conv2_b, x, xr);  // xr = conv2 + x

    // Self-attention
    gn_kernel<<<BB * NGRP, 256>>>(xr, gnA_s, gnA_b, a, 0);
    gemm_kernel<<<dim3(HWSZ / 64, 12, BB), 256>>>(qkv_w, a, (const float*)0, (const float*)0,
                                                  qkv, 3 * CC);
    attn_kernel<<<dim3(HWSZ / 64, BB), 256, attn_smem>>>(qkv, ao);
    gemm_kernel<<<dim3(HWSZ / 64, 4, BB), 256>>>(out_w, ao, out_b, xr, out, CC);
}

// round 2
// speedup vs baseline: 2.0907x; 2.0907x over previous
#include <cuda_runtime.h>
#include <math.h>

// Problem constants
#define BB    4
#define CC    256
#define HWSZ  4096
#define CPG   8

// ---------------- scratch (device globals; no allocation allowed) ----------------
__device__ float g_a  [BB*CC*HWSZ];        // groupnorm(+silu) output
__device__ float g_h  [BB*CC*HWSZ];        // conv1 output
__device__ float g_xr [BB*CC*HWSZ];        // residual branch output
__device__ float g_qkv[BB*3*CC*HWSZ];      // qkv projections [b][3C][HW]
__device__ float g_ao [BB*CC*HWSZ];        // attention output [b][C][HW]
__device__ float g_gb [BB*2*CC];           // FiLM gamma/beta
__device__ float g_col[(size_t)BB*2304*HWSZ];     // im2col buffer
__device__ float g_S  [(size_t)BB*HWSZ*HWSZ];     // scores St[t][s] per batch
__device__ float g_rdx[BB*2*HWSZ];         // per-column max / invsum

// ---------------- GroupNorm (+ optional SiLU), float4 vectorized ----------------
// grid: B*32 blocks, 256 threads
__global__ void gn_kernel(const float* __restrict__ x, const float* __restrict__ sc,
                          const float* __restrict__ bi, float* __restrict__ y, int dosilu) {
    __shared__ float rs[256], rq[256];
    __shared__ float mv[2];
    int bg = blockIdx.x;
    int b = bg >> 5, g = bg & 31;
    const float4* xp = (const float4*)(x + (size_t)(b * CC + g * CPG) * HWSZ);
    float4* yp = (float4*)(y + (size_t)(b * CC + g * CPG) * HWSZ);
    int tid = threadIdx.x;
    float sum = 0.f, sq = 0.f;
    for (int i = tid; i < 8192; i += 256) {
        float4 v = xp[i];
        sum += v.x + v.y + v.z + v.w;
        sq += v.x*v.x + v.y*v.y + v.z*v.z + v.w*v.w;
    }
    rs[tid] = sum; rq[tid] = sq;
    __syncthreads();
    for (int st = 128; st > 0; st >>= 1) {
        if (tid < st) { rs[tid] += rs[tid + st]; rq[tid] += rq[tid + st]; }
        __syncthreads();
    }
    if (tid == 0) {
        float m = rs[0] * (1.f / 32768.f);
        float var = rq[0] * (1.f / 32768.f) - m * m;
        mv[0] = m; mv[1] = rsqrtf(var + 1e-5f);
    }
    __syncthreads();
    float m = mv[0], inv = mv[1];
    for (int i = tid; i < 8192; i += 256) {
        int c = g * CPG + (i >> 10);
        float a = inv * sc[c], bb = bi[c] - m * a;
        float4 v = xp[i];
        v.x = v.x * a + bb; v.y = v.y * a + bb; v.z = v.z * a + bb; v.w = v.w * a + bb;
        if (dosilu) {
            v.x = v.x / (1.f + __expf(-v.x));
            v.y = v.y / (1.f + __expf(-v.y));
            v.z = v.z / (1.f + __expf(-v.z));
            v.w = v.w / (1.f + __expf(-v.w));
        }
        yp[i] = v;
    }
}

// ---------------- im2col: col[b][ic*9+k][p] = x[b][ic][p shifted by k] ----------------
// grid (4, 2304, B), block 256, 4 px per thread
__global__ void im2col_kernel(const float* __restrict__ x, float* __restrict__ col) {
    int p = (blockIdx.x * 256 + threadIdx.x) * 4;
    int ck = blockIdx.y, b = blockIdx.z;
    int ic = ck / 9, k = ck - ic * 9;
    int kh = k / 3 - 1, kw = k - (k / 3) * 3 - 1;
    int h = p >> 6, w = p & 63;
    int h2 = h + kh;
    float4 v = make_float4(0.f, 0.f, 0.f, 0.f);
    if ((unsigned)h2 < 64u) {
        const float* base = x + ((size_t)(b * CC + ic) << 12) + (h2 << 6);
        float* ve = (float*)&v;
        #pragma unroll
        for (int e = 0; e < 4; e++) {
            int w2 = w + e + kw;
            if ((unsigned)w2 < 64u) ve[e] = base[w2];
        }
    }
    *(float4*)&col[(size_t)b * 2304 * HWSZ + (size_t)ck * HWSZ + p] = v;
}

// ---------------- FiLM mlp: gb[b,j] = silu(te[b,:]) . mlp_w[j,:] + mlp_b[j] ----------------
__global__ void film_mlp_kernel(const float* __restrict__ te, const float* __restrict__ w,
                                const float* __restrict__ bi, float* __restrict__ gb) {
    __shared__ float s_te[256];
    int b = blockIdx.x, tid = threadIdx.x;
    for (int i = tid; i < 256; i += 128) {
        float v = te[b * 256 + i];
        s_te[i] = v / (1.f + __expf(-v));
    }
    __syncthreads();
    int j = blockIdx.y * 128 + tid;
    const float* wr = w + (size_t)j * 256;
    float acc = bi[j];
    for (int t = 0; t < 256; t++) acc += s_te[t] * wr[t];
    gb[b * 512 + j] = acc;
}

// ---------------- generic 128x128 GEMM with fused epilogues ----------------
// Y[b][o][p] = alpha * sum_k A[o][k] (or A[k][o] if aCol) * X[b][k][p]
//   then + bias[o];   then film: (1+gamma[b,o])*v + beta[b,o];
//   then * cscale[b][p];   then + res[b][o][p]
// N fixed = 4096 (row stride of X, Y, res). K % 16 == 0, M % 128 == 0.
__global__ void __launch_bounds__(256, 2) gemm128_kernel(
    const float* __restrict__ A, const float* __restrict__ X, float* __restrict__ Y,
    int K, int aCol, int lda,
    long long strideA, long long strideX, long long strideY,
    const float* __restrict__ bias,
    const float* __restrict__ film,
    const float* __restrict__ res, long long strideRes,
    const float* __restrict__ cscale, long long strideCS,
    float alpha) {
    __shared__ float sA[2][16][132];
    __shared__ float sB[2][16][132];
    int b = blockIdx.z;
    const float* Ab = A + strideA * b;
    const float* Xb = X + strideX * b;
    float* Yb = Y + strideY * b;
    int o0 = blockIdx.y * 128, p0 = blockIdx.x * 128;
    int tid = threadIdx.x, tx = tid & 15, ty = tid >> 4;

    unsigned long long acc[8][4];
    #pragma unroll
    for (int i = 0; i < 8; i++)
        #pragma unroll
        for (int j = 0; j < 4; j++) acc[i][j] = 0ull;

    // initial tile (k0 = 0) into buffer 0
    if (aCol) {
        #pragma unroll
        for (int r = 0; r < 2; r++) {
            int f = tid + r * 256, kk = f >> 5, o4 = f & 31;
            float4 v = *(const float4*)&Ab[(size_t)kk * lda + o0 + o4 * 4];
            *(float4*)&sA[0][kk][o4 * 4] = v;
        }
    } else {
        #pragma unroll
        for (int r = 0; r < 2; r++) {
            int f = tid + r * 256, o = f >> 2, kq = f & 3;
            float4 v = *(const float4*)&Ab[(size_t)(o0 + o) * lda + kq * 4];
            sA[0][kq * 4 + 0][o] = v.x; sA[0][kq * 4 + 1][o] = v.y;
            sA[0][kq * 4 + 2][o] = v.z; sA[0][kq * 4 + 3][o] = v.w;
        }
    }
    #pragma unroll
    for (int r = 0; r < 2; r++) {
        int f = tid + r * 256, kk = f >> 5, p4 = f & 31;
        float4 v = *(const float4*)&Xb[(size_t)kk * 4096 + p0 + p4 * 4];
        *(float4*)&sB[0][kk][p4 * 4] = v;
    }
    __syncthreads();

    int nk = K >> 4;
    int cur = 0;
    for (int kt = 0; kt < nk; kt++) {
        float4 ra0, ra1, rb0, rb1;
        bool has = (kt + 1 < nk);
        int k0n = (kt + 1) << 4;
        if (has) {
            if (aCol) {
                { int f = tid;       int kk = f >> 5, o4 = f & 31; ra0 = *(const float4*)&Ab[(size_t)(k0n + kk) * lda + o0 + o4 * 4]; }
                { int f = tid + 256; int kk = f >> 5, o4 = f & 31; ra1 = *(const float4*)&Ab[(size_t)(k0n + kk) * lda + o0 + o4 * 4]; }
            } else {
                { int f = tid;       int o = f >> 2, kq = f & 3; ra0 = *(const float4*)&Ab[(size_t)(o0 + o) * lda + k0n + kq * 4]; }
                { int f = tid + 256; int o = f >> 2, kq = f & 3; ra1 = *(const float4*)&Ab[(size_t)(o0 + o) * lda + k0n + kq * 4]; }
            }
            { int f = tid;       int kk = f >> 5, p4 = f & 31; rb0 = *(const float4*)&Xb[(size_t)(k0n + kk) * 4096 + p0 + p4 * 4]; }
            { int f = tid + 256; int kk = f >> 5, p4 = f & 31; rb1 = *(const float4*)&Xb[(size_t)(k0n + kk) * 4096 + p0 + p4 * 4]; }
        }
        #pragma unroll
        for (int kk = 0; kk < 16; kk++) {
            float4 a0 = *(const float4*)&sA[cur][kk][ty * 8];
            float4 a1 = *(const float4*)&sA[cur][kk][ty * 8 + 4];
            ulonglong2 bl = *(const ulonglong2*)&sB[cur][kk][tx * 8];
            ulonglong2 bh = *(const ulonglong2*)&sB[cur][kk][tx * 8 + 4];
            unsigned long long bp[4] = { bl.x, bl.y, bh.x, bh.y };
            float av[8] = { a0.x, a0.y, a0.z, a0.w, a1.x, a1.y, a1.z, a1.w };
            #pragma unroll
            for (int i = 0; i < 8; i++) {
                unsigned long long ad;
                asm("mov.b64 %0, {%1, %2};" : "=l"(ad) : "f"(av[i]), "f"(av[i]));
                #pragma unroll
                for (int j = 0; j < 4; j++)
                    asm("fma.rn.f32x2 %0, %1, %2, %0;" : "+l"(acc[i][j]) : "l"(ad), "l"(bp[j]));
            }
        }
        if (has) {
            int nb = cur ^ 1;
            if (aCol) {
                { int f = tid;       int kk = f >> 5, o4 = f & 31; *(float4*)&sA[nb][kk][o4 * 4] = ra0; }
                { int f = tid + 256; int kk = f >> 5, o4 = f & 31; *(float4*)&sA[nb][kk][o4 * 4] = ra1; }
            } else {
                { int f = tid;       int o = f >> 2, kq = f & 3;
                  sA[nb][kq * 4 + 0][o] = ra0.x; sA[nb][kq * 4 + 1][o] = ra0.y;
                  sA[nb][kq * 4 + 2][o] = ra0.z; sA[nb][kq * 4 + 3][o] = ra0.w; }
                { int f = tid + 256; int o = f >> 2, kq = f & 3;
                  sA[nb][kq * 4 + 0][o] = ra1.x; sA[nb][kq * 4 + 1][o] = ra1.y;
                  sA[nb][kq * 4 + 2][o] = ra1.z; sA[nb][kq * 4 + 3][o] = ra1.w; }
            }
            { int f = tid;       int kk = f >> 5, p4 = f & 31; *(float4*)&sB[nb][kk][p4 * 4] = rb0; }
            { int f = tid + 256; int kk = f >> 5, p4 = f & 31; *(float4*)&sB[nb][kk][p4 * 4] = rb1; }
            __syncthreads();
            cur = nb;
        }
    }

    // epilogue
    float cs[8];
    if (cscale) {
        #pragma unroll
        for (int j = 0; j < 8; j++)
            cs[j] = cscale[(size_t)b * strideCS + p0 + tx * 8 + j];
    }
    #pragma unroll
    for (int i = 0; i < 8; i++) {
        int o = o0 + ty * 8 + i;
        float bv = bias ? bias[o] : 0.f;
        float g = 0.f, bt = 0.f;
        if (film) { g = film[(size_t)b * 512 + o]; bt = film[(size_t)b * 512 + 256 + o]; }
        float vo[8];
        #pragma unroll
        for (int jp = 0; jp < 4; jp++) {
            float lo, hi;
            asm("mov.b64 {%0, %1}, %2;" : "=f"(lo), "=f"(hi) : "l"(acc[i][jp]));
            vo[2 * jp] = lo; vo[2 * jp + 1] = hi;
        }
        size_t yrow = (size_t)o * 4096 + p0 + tx * 8;
        #pragma unroll
        for (int j = 0; j < 8; j++) {
            float v = vo[j] * alpha + bv;
            if (film) v = (1.f + g) * v + bt;
            if (cscale) v *= cs[j];
            if (res) v += res[(size_t)b * strideRes + yrow + j];
            vo[j] = v;
        }
        *(float4*)&Yb[yrow]     = make_float4(vo[0], vo[1], vo[2], vo[3]);
        *(float4*)&Yb[yrow + 4] = make_float4(vo[4], vo[5], vo[6], vo[7]);
    }
}

// ---------------- column softmax over St[t][s] (softmax over t per column s) ----------------
// grid (32, B), block 128
__global__ void smax_max_kernel(const float* __restrict__ S, float* __restrict__ rdx) {
    int s = blockIdx.x * 128 + threadIdx.x;
    int b = blockIdx.y;
    const float* Sb = S + (size_t)b * HWSZ * HWSZ;
    float m0 = -1e30f, m1 = -1e30f, m2 = -1e30f, m3 = -1e30f;
    #pragma unroll 2
    for (int t = 0; t < HWSZ; t += 4) {
        m0 = fmaxf(m0, Sb[(size_t)(t + 0) * 4096 + s]);
        m1 = fmaxf(m1, Sb[(size_t)(t + 1) * 4096 + s]);
        m2 = fmaxf(m2, Sb[(size_t)(t + 2) * 4096 + s]);
        m3 = fmaxf(m3, Sb[(size_t)(t + 3) * 4096 + s]);
    }
    rdx[b * 8192 + s] = fmaxf(fmaxf(m0, m1), fmaxf(m2, m3));
}

__global__ void smax_exp_kernel(float* __restrict__ S, float* __restrict__ rdx) {
    int s = blockIdx.x * 128 + threadIdx.x;
    int b = blockIdx.y;
    float* Sb = S + (size_t)b * HWSZ * HWSZ;
    float mx = rdx[b * 8192 + s];
    float s0 = 0.f, s1 = 0.f, s2 = 0.f, s3 = 0.f;
    #pragma unroll 2
    for (int t = 0; t < HWSZ; t += 4) {
        size_t i0 = (size_t)(t + 0) * 4096 + s;
        size_t i1 = (size_t)(t + 1) * 4096 + s;
        size_t i2 = (size_t)(t + 2) * 4096 + s;
        size_t i3 = (size_t)(t + 3) * 4096 + s;
        float e0 = __expf(Sb[i0] - mx); Sb[i0] = e0; s0 += e0;
        float e1 = __expf(Sb[i1] - mx); Sb[i1] = e1; s1 += e1;
        float e2 = __expf(Sb[i2] - mx); Sb[i2] = e2; s2 += e2;
        float e3 = __expf(Sb[i3] - mx); Sb[i3] = e3; s3 += e3;
    }
    rdx[b * 8192 + 4096 + s] = 1.f / ((s0 + s1) + (s2 + s3));
}

// ---------------- host launch ----------------
extern "C" void kernel_launch(void* const* d_in, const int* in_sizes, int n_in,
                              void* d_out, int out_size) {
    const float* x       = (const float*)d_in[0];
    const float* te      = (const float*)d_in[1];
    const float* gn1_s   = (const float*)d_in[2];
    const float* gn1_b   = (const float*)d_in[3];
    const float* conv1_w = (const float*)d_in[4];
    const float* conv1_b = (const float*)d_in[5];
    const float* mlp_w   = (const float*)d_in[6];
    const float* mlp_b   = (const float*)d_in[7];
    const float* gn2_s   = (const float*)d_in[8];
    const float* gn2_b   = (const float*)d_in[9];
    const float* conv2_w = (const float*)d_in[10];
    const float* conv2_b = (const float*)d_in[11];
    const float* gnA_s   = (const float*)d_in[12];
    const float* gnA_b   = (const float*)d_in[13];
    const float* qkv_w   = (const float*)d_in[14];
    const float* out_w   = (const float*)d_in[15];
    const float* out_b   = (const float*)d_in[16];
    float* out = (float*)d_out;

    float *a, *h, *xr, *qkv, *ao, *gb, *col, *S, *rdx;
    cudaGetSymbolAddress((void**)&a,   g_a);
    cudaGetSymbolAddress((void**)&h,   g_h);
    cudaGetSymbolAddress((void**)&xr,  g_xr);
    cudaGetSymbolAddress((void**)&qkv, g_qkv);
    cudaGetSymbolAddress((void**)&ao,  g_ao);
    cudaGetSymbolAddress((void**)&gb,  g_gb);
    cudaGetSymbolAddress((void**)&col, g_col);
    cudaGetSymbolAddress((void**)&S,   g_S);
    cudaGetSymbolAddress((void**)&rdx, g_rdx);

    const long long CHW = 1LL << 20;       // C*HW
    const long long COLS = 2304LL * 4096;  // im2col per-batch
    const long long SST = 1LL << 24;       // HW*HW

    // FiLM gamma/beta (independent; launch early)
    film_mlp_kernel<<<dim3(BB, 4), 128>>>(te, mlp_w, mlp_b, gb);

    // ---- conv1: gn1+silu -> im2col -> GEMM (+bias, +FiLM) ----
    gn_kernel<<<BB * 32, 256>>>(x, gn1_s, gn1_b, a, 1);
    im2col_kernel<<<dim3(4, 2304, BB), 256>>>(a, col);
    gemm128_kernel<<<dim3(32, 2, BB), 256>>>(
        conv1_w, col, h, 2304, 0, 2304, 0LL, COLS, CHW,
        conv1_b, gb, (const float*)0, 0LL, (const float*)0, 0LL, 1.f);

    // ---- conv2: gn2+silu -> im2col -> GEMM (+bias, +x residual) -> xr ----
    gn_kernel<<<BB * 32, 256>>>(h, gn2_s, gn2_b, a, 1);
    im2col_kernel<<<dim3(4, 2304, BB), 256>>>(a, col);
    gemm128_kernel<<<dim3(32, 2, BB), 256>>>(
        conv2_w, col, xr, 2304, 0, 2304, 0LL, COLS, CHW,
        conv2_b, (const float*)0, x, CHW, (const float*)0, 0LL, 1.f);

    // ---- attention ----
    gn_kernel<<<BB * 32, 256>>>(xr, gnA_s, gnA_b, a, 0);
    // qkv = qkv_w @ a
    gemm128_kernel<<<dim3(32, 6, BB), 256>>>(
        qkv_w, a, qkv, 256, 0, 256, 0LL, CHW, 3 * CHW,
        (const float*)0, (const float*)0, (const float*)0, 0LL, (const float*)0, 0LL, 1.f);
    // St[t][s] = sum_c K[c][t] * Q[c][s] / 16
    gemm128_kernel<<<dim3(32, 32, BB), 256>>>(
        qkv + CHW, qkv, S, 256, 1, 4096, 3 * CHW, 3 * CHW, SST,
        (const float*)0, (const float*)0, (const float*)0, 0LL, (const float*)0, 0LL, 0.0625f);
    // column softmax over t
    smax_max_kernel<<<dim3(32, BB), 128>>>(S, rdx);
    smax_exp_kernel<<<dim3(32, BB), 128>>>(S, rdx);
    // ao[d][s] = sum_t V[d][t] * P[t][s] * invsum[s]
    gemm128_kernel<<<dim3(32, 2, BB), 256>>>(
        qkv + 2 * CHW, S, ao, 4096, 0, 4096, 3 * CHW, SST, CHW,
        (const float*)0, (const float*)0, (const float*)0, 0LL, rdx + 4096, 8192LL, 1.f);
    // out = out_w @ ao + out_b + xr
    gemm128_kernel<<<dim3(32, 2, BB), 256>>>(
        out_w, ao, out, 256, 0, 256, 0LL, CHW, CHW,
        out_b, (const float*)0, xr, CHW, (const float*)0, 0LL, 1.f);
}